// round 15
// baseline (speedup 1.0000x reference)
#include <cuda_runtime.h>

#define NN 100000
#define EE 3200000

typedef unsigned long long u64;

// ---------------- scratch (device globals; no dynamic allocation) ----------------
// per-node dest record: {acc0..3, denom, pad...}  (32B)
__device__ __align__(128) float g_dr[NN * 8];
__device__ __align__(16) float g_acc2[NN * 4];    // layer2: {sum ex*h20, sum ex*h21, sum ex, pad}
__device__ __align__(128) float g_psrc[NN * 16];  // h1 @ mw0[0:16]   (64B records)
__device__ __align__(128) float g_pdst[NN * 16];  // h1 @ mw0[19:35]  (64B records)
__device__ __align__(16) float g_sd2[NN * 4];     // {h20, h21, al2s, al2d}
__device__ __align__(16) float g_easum_part[256 * 4];
__device__ __align__(16) float g_esum_part[256 * 4];
__device__ __align__(16) float g_c1[4];           // We1 @ ae1
__device__ __align__(16) float g_c2[4];           // We2 @ ae2
__device__ __align__(16) float g_wal[4];          // W1 @ as1
__device__ __align__(16) float g_wad[4];          // W1 @ ad1

// ---------------- helpers ----------------
__device__ __forceinline__ float leaky(float x) { return x > 0.f ? x : 0.2f * x; }

__device__ __forceinline__ u64 pack2(float x) {
    u64 r; asm("mov.b64 %0, {%1, %1};" : "=l"(r) : "f"(x)); return r;
}
__device__ __forceinline__ u64 fma2(u64 a, u64 b, u64 c) {
    u64 d; asm("fma.rn.f32x2 %0, %1, %2, %3;" : "=l"(d) : "l"(a), "l"(b), "l"(c)); return d;
}
__device__ __forceinline__ void unpack2(u64 a, float& x, float& y) {
    asm("mov.b64 {%0, %1}, %2;" : "=f"(x), "=f"(y) : "l"(a));
}
__device__ __forceinline__ void red_v4(float* p, float a, float b, float c, float d) {
    asm volatile("red.global.add.v4.f32 [%0], {%1, %2, %3, %4};"
                 :: "l"(p), "f"(a), "f"(b), "f"(c), "f"(d) : "memory");
}
__device__ __forceinline__ void red_f32(float* p, float v) {
    asm volatile("red.global.add.f32 [%0], %1;" :: "l"(p), "f"(v) : "memory");
}

// ---------------- K1: zero accumulators + constants (block 0) ----------------
__global__ void __launch_bounds__(256) k_node1(const float* __restrict__ W1,
                                               const float* __restrict__ as1,
                                               const float* __restrict__ ad1,
                                               const float* __restrict__ We1,
                                               const float* __restrict__ ae1,
                                               const float* __restrict__ We2,
                                               const float* __restrict__ ae2) {
    int t = threadIdx.x;
    if (blockIdx.x == 0) {
        if (t < 3) {
            float s = 0.f;
            #pragma unroll
            for (int k = 0; k < 16; k++) s += We1[t * 16 + k] * ae1[k];
            g_c1[t] = s;
        }
        if (t == 3) g_c1[3] = 0.f;
        if (t >= 4 && t < 8) {
            int j = t - 4;
            g_c2[j] = We2[j * 2] * ae2[0] + We2[j * 2 + 1] * ae2[1];
        }
        if (t >= 8 && t < 12) {
            int j = t - 8;
            float sA = 0.f, sD = 0.f;
            #pragma unroll
            for (int k = 0; k < 16; k++) {
                sA += W1[j * 16 + k] * as1[k];
                sD += W1[j * 16 + k] * ad1[k];
            }
            g_wal[j] = sA;
            g_wad[j] = sD;
        }
    }
    int n = blockIdx.x * 256 + t;
    float4 z = make_float4(0.f, 0.f, 0.f, 0.f);
    if (n < 256) {
        reinterpret_cast<float4*>(g_easum_part)[n] = z;
        reinterpret_cast<float4*>(g_esum_part)[n] = z;
    }
    if (n >= NN) return;
    reinterpret_cast<float4*>(g_dr)[n * 2] = z;
    reinterpret_cast<float4*>(g_dr)[n * 2 + 1] = z;
    reinterpret_cast<float4*>(g_acc2)[n] = z;
}

// ---------------- K2: layer-1 edge pass (scatter ex*x[s]) + warp-level ea sums ----------------
__global__ void __launch_bounds__(256) k_edge1(const int* __restrict__ src,
                                               const int* __restrict__ dst,
                                               const float* __restrict__ ea,
                                               const float* __restrict__ x) {
    int t = threadIdx.x;
    int e = blockIdx.x * 256 + t;  // grid covers EE exactly
    int s = src[e], d = dst[e];
    float ea0 = ea[e * 3], ea1 = ea[e * 3 + 1], ea2 = ea[e * 3 + 2];
    float4 xs = reinterpret_cast<const float4*>(x)[s];
    float4 xd = reinterpret_cast<const float4*>(x)[d];
    float4 wl = *reinterpret_cast<const float4*>(g_wal);
    float4 wd = *reinterpret_cast<const float4*>(g_wad);
    float4 c1 = *reinterpret_cast<const float4*>(g_c1);
    float als = xs.x * wl.x + xs.y * wl.y + xs.z * wl.z + xs.w * wl.w;
    float ald = xd.x * wd.x + xd.y * wd.y + xd.z * wd.z + xd.w * wd.w;
    float a = als + ald + ea0 * c1.x + ea1 * c1.y + ea2 * c1.z;
    float ex = __expf(leaky(a));
    float* dr = g_dr + (size_t)d * 8;
    red_v4(dr, ex * xs.x, ex * xs.y, ex * xs.z, ex * xs.w);
    red_f32(dr + 4, ex);

    // per-warp edge_attr sum -> distributed partials (no barrier)
    float s0 = ea0, s1 = ea1, s2 = ea2;
    #pragma unroll
    for (int o = 16; o > 0; o >>= 1) {
        s0 += __shfl_down_sync(0xffffffffu, s0, o);
        s1 += __shfl_down_sync(0xffffffffu, s1, o);
        s2 += __shfl_down_sync(0xffffffffu, s2, o);
    }
    if ((t & 31) == 0) {
        int slot = (blockIdx.x * 8 + (t >> 5)) & 255;
        red_v4(g_easum_part + slot * 4, s0, s1, s2, 0.f);
    }
}

// ---------------- K3: finalize layer 1 + derive per-node layer-2 quantities ----------------
__global__ void __launch_bounds__(256) k_node2(const float* __restrict__ x,
                                               const float* __restrict__ W1,
                                               const float* __restrict__ b1,
                                               const float* __restrict__ mw0,
                                               const float* __restrict__ W2,
                                               const float* __restrict__ as2,
                                               const float* __restrict__ ad2) {
    __shared__ float sws[256];  // mw0 rows 0..15
    __shared__ float swd[256];  // mw0 rows 19..34
    __shared__ float sW1[64], sb1[16], sW2[32], sas2[2], sad2[2];
    __shared__ float4 redsh[8];
    int t = threadIdx.x;
    // inline easum reduce (all blocks, redundant, cheap)
    {
        float4 v = reinterpret_cast<const float4*>(g_easum_part)[t];
        #pragma unroll
        for (int o = 16; o > 0; o >>= 1) {
            v.x += __shfl_down_sync(0xffffffffu, v.x, o);
            v.y += __shfl_down_sync(0xffffffffu, v.y, o);
            v.z += __shfl_down_sync(0xffffffffu, v.z, o);
        }
        if ((t & 31) == 0) redsh[t >> 5] = v;
    }
    sws[t] = mw0[t];
    swd[t] = mw0[19 * 16 + t];
    if (t < 64) sW1[t] = W1[t];
    if (t >= 64 && t < 80) sb1[t - 64] = b1[t - 64];
    if (t >= 80 && t < 112) sW2[t - 80] = W2[t - 80];
    if (t >= 112 && t < 114) sas2[t - 112] = as2[t - 112];
    if (t >= 114 && t < 116) sad2[t - 114] = ad2[t - 114];
    __syncthreads();
    float m0, m1, m2;
    {
        float4 r = redsh[0];
        #pragma unroll
        for (int i = 1; i < 8; i++) { r.x += redsh[i].x; r.y += redsh[i].y; r.z += redsh[i].z; }
        const float invE = 1.f / (float)EE;
        m0 = r.x * invE; m1 = r.y * invE; m2 = r.z * invE;
    }
    int n = blockIdx.x * 256 + t;
    if (n >= NN) return;

    float4 xv = reinterpret_cast<const float4*>(x)[n];
    float4 wl = *reinterpret_cast<const float4*>(g_wal);
    float4 wd = *reinterpret_cast<const float4*>(g_wad);
    float als = xv.x * wl.x + xv.y * wl.y + xv.z * wl.z + xv.w * wl.w;
    float ald = xv.x * wd.x + xv.y * wd.y + xv.z * wd.z + xv.w * wd.w;
    float aself = leaky(als + ald + m0 * g_c1[0] + m1 * g_c1[1] + m2 * g_c1[2]);
    float ex = __expf(aself);
    const float* dr = g_dr + (size_t)n * 8;
    float inv = 1.f / (dr[4] + ex + 1e-16f);

    float4 acc = *reinterpret_cast<const float4*>(dr);
    acc.x += ex * xv.x;
    acc.y += ex * xv.y;
    acc.z += ex * xv.z;
    acc.w += ex * xv.w;

    float h1[16];
    #pragma unroll
    for (int j = 0; j < 16; j++) {
        float h = acc.x * sW1[j] + acc.y * sW1[16 + j] + acc.z * sW1[32 + j] + acc.w * sW1[48 + j];
        h1[j] = h * inv + sb1[j];
    }

    float ps[16], pd[16];
    #pragma unroll
    for (int j = 0; j < 16; j++) {
        float a0 = 0.f, a1 = 0.f;
        #pragma unroll
        for (int i = 0; i < 16; i++) {
            a0 += h1[i] * sws[i * 16 + j];
            a1 += h1[i] * swd[i * 16 + j];
        }
        ps[j] = a0;
        pd[j] = a1;
    }
    float h20 = 0.f, h21 = 0.f;
    #pragma unroll
    for (int i = 0; i < 16; i++) {
        h20 += h1[i] * sW2[i * 2];
        h21 += h1[i] * sW2[i * 2 + 1];
    }
    float al2s = h20 * sas2[0] + h21 * sas2[1];
    float al2d = h20 * sad2[0] + h21 * sad2[1];

    float4* pp = reinterpret_cast<float4*>(g_psrc + (size_t)n * 16);
    #pragma unroll
    for (int q = 0; q < 4; q++)
        pp[q] = make_float4(ps[4 * q], ps[4 * q + 1], ps[4 * q + 2], ps[4 * q + 3]);
    float4* pq = reinterpret_cast<float4*>(g_pdst + (size_t)n * 16);
    #pragma unroll
    for (int q = 0; q < 4; q++)
        pq[q] = make_float4(pd[4 * q], pd[4 * q + 1], pd[4 * q + 2], pd[4 * q + 3]);
    reinterpret_cast<float4*>(g_sd2)[n] = make_float4(h20, h21, al2s, al2d);
}

// ---------------- K4: edge MLP, persistent CTAs + two-phase cooperative gather ----------------
#define EPB 512
#define NCHUNK (EE / EPB)   // 6250
#define PGRID 444           // 3 blocks/SM x 148 SMs
__global__ void __launch_bounds__(256) k_edge2(const int* __restrict__ src,
                                               const int* __restrict__ dst,
                                               const float* __restrict__ ea,
                                               const float* __restrict__ mw0,
                                               const float* __restrict__ mb0,
                                               const float* __restrict__ mw1,
                                               const float* __restrict__ mb1,
                                               const float* __restrict__ mw2,
                                               const float* __restrict__ mb2,
                                               const float* __restrict__ mw3,
                                               const float* __restrict__ mb3,
                                               float* __restrict__ out_e) {
    __shared__ __align__(16) float4 s_w0q[12];      // mw0 rows 16..18, by quarter
    __shared__ __align__(16) float4 s_b0q[4];
    __shared__ __align__(16) ulonglong2 s_w1v[64];
    __shared__ __align__(16) ulonglong2 s_b1v[4];
    __shared__ __align__(16) ulonglong2 s_w2v[32];
    __shared__ __align__(16) ulonglong2 s_b2v[2];
    __shared__ __align__(16) ulonglong2 s_w3v[8];
    __shared__ __align__(16) ulonglong2 s_b3v[1];
    __shared__ float s_c2[4];
    __shared__ __align__(16) float s_t0[EPB * 20];  // staged t0, 80B stride (16B aligned)
    __shared__ int s_sidx[EPB];
    __shared__ int s_didx[EPB];

    int t = threadIdx.x;
    if (t < 12) s_w0q[t] = reinterpret_cast<const float4*>(mw0)[64 + t];
    else if (t < 16) s_b0q[t - 12] = reinterpret_cast<const float4*>(mb0)[t - 12];
    else if (t < 80) s_w1v[t - 16] = reinterpret_cast<const ulonglong2*>(mw1)[t - 16];
    else if (t < 84) s_b1v[t - 80] = reinterpret_cast<const ulonglong2*>(mb1)[t - 80];
    else if (t < 116) s_w2v[t - 84] = reinterpret_cast<const ulonglong2*>(mw2)[t - 84];
    else if (t < 118) s_b2v[t - 116] = reinterpret_cast<const ulonglong2*>(mb2)[t - 116];
    else if (t < 126) s_w3v[t - 118] = reinterpret_cast<const ulonglong2*>(mw3)[t - 118];
    else if (t < 127) s_b3v[0] = reinterpret_cast<const ulonglong2*>(mb3)[0];
    if (t >= 128 && t < 132) s_c2[t - 128] = g_c2[t - 128];
    __syncthreads();

    float esum0 = 0.f, esum1 = 0.f, esum2 = 0.f, esum3 = 0.f;

    for (int chunk = blockIdx.x; chunk < NCHUNK; chunk += PGRID) {
        int ebase = chunk * EPB;

        // ---- phase 1: cooperative gather (4 lanes per edge, 64 edges/pass) + layer 0 ----
        {
            int q = t & 3;
            int er = t >> 2;  // 0..63
            float4 w0a = s_w0q[q], w0b = s_w0q[4 + q], w0c = s_w0q[8 + q], b0 = s_b0q[q];
            #pragma unroll
            for (int k = 0; k < 8; k++) {
                int el = k * 64 + er;
                int e = ebase + el;
                int s = src[e], d = dst[e];
                float ea0 = ea[e * 3], ea1 = ea[e * 3 + 1], ea2 = ea[e * 3 + 2];
                float4 ps = *reinterpret_cast<const float4*>(g_psrc + (size_t)s * 16 + q * 4);
                float4 pd = *reinterpret_cast<const float4*>(g_pdst + (size_t)d * 16 + q * 4);
                float4 v;
                v.x = fmaxf(ps.x + pd.x + b0.x + ea0 * w0a.x + ea1 * w0b.x + ea2 * w0c.x, 0.f);
                v.y = fmaxf(ps.y + pd.y + b0.y + ea0 * w0a.y + ea1 * w0b.y + ea2 * w0c.y, 0.f);
                v.z = fmaxf(ps.z + pd.z + b0.z + ea0 * w0a.z + ea1 * w0b.z + ea2 * w0c.z, 0.f);
                v.w = fmaxf(ps.w + pd.w + b0.w + ea0 * w0a.w + ea1 * w0b.w + ea2 * w0c.w, 0.f);
                *reinterpret_cast<float4*>(s_t0 + el * 20 + q * 4) = v;
                if (q == 0) {
                    s_sidx[el] = s;
                    s_didx[el] = d;
                }
            }
        }
        __syncthreads();

        // ---- phase 2: layers 1-3 for 2 edges/thread ----
        int eA = ebase + t;
        int eB = eA + 256;
        float t0A[16], t0B[16];
        {
            const float4* pA = reinterpret_cast<const float4*>(s_t0 + t * 20);
            const float4* pB = reinterpret_cast<const float4*>(s_t0 + (t + 256) * 20);
            #pragma unroll
            for (int qq = 0; qq < 4; qq++) {
                float4 a = pA[qq], b = pB[qq];
                t0A[4 * qq] = a.x; t0A[4 * qq + 1] = a.y; t0A[4 * qq + 2] = a.z; t0A[4 * qq + 3] = a.w;
                t0B[4 * qq] = b.x; t0B[4 * qq + 1] = b.y; t0B[4 * qq + 2] = b.z; t0B[4 * qq + 3] = b.w;
            }
        }
        int sA = s_sidx[t], dA = s_didx[t];
        int sB = s_sidx[t + 256], dB = s_didx[t + 256];
        float4 sdA = reinterpret_cast<const float4*>(g_sd2)[sA];  // {h20,h21,al2s,al2d}
        float4 sdB = reinterpret_cast<const float4*>(g_sd2)[sB];
        float ald2A = g_sd2[(size_t)dA * 4 + 3];
        float ald2B = g_sd2[(size_t)dB * 4 + 3];

        // layer 1: 16 -> 16
        u64 accA[8], accB[8];
        #pragma unroll
        for (int qq = 0; qq < 4; qq++) {
            ulonglong2 b = s_b1v[qq];
            accA[2 * qq] = b.x; accA[2 * qq + 1] = b.y;
            accB[2 * qq] = b.x; accB[2 * qq + 1] = b.y;
        }
        #pragma unroll
        for (int i = 0; i < 16; i++) {
            u64 biA = pack2(t0A[i]), biB = pack2(t0B[i]);
            #pragma unroll
            for (int qq = 0; qq < 4; qq++) {
                ulonglong2 w = s_w1v[i * 4 + qq];
                accA[2 * qq] = fma2(biA, w.x, accA[2 * qq]);
                accA[2 * qq + 1] = fma2(biA, w.y, accA[2 * qq + 1]);
                accB[2 * qq] = fma2(biB, w.x, accB[2 * qq]);
                accB[2 * qq + 1] = fma2(biB, w.y, accB[2 * qq + 1]);
            }
        }
        float t1A[16], t1B[16];
        #pragma unroll
        for (int p = 0; p < 8; p++) {
            float lo, hi;
            unpack2(accA[p], lo, hi); t1A[2 * p] = fmaxf(lo, 0.f); t1A[2 * p + 1] = fmaxf(hi, 0.f);
            unpack2(accB[p], lo, hi); t1B[2 * p] = fmaxf(lo, 0.f); t1B[2 * p + 1] = fmaxf(hi, 0.f);
        }

        // layer 2: 16 -> 8
        u64 c2A[4], c2B[4];
        {
            ulonglong2 b0 = s_b2v[0], b1 = s_b2v[1];
            c2A[0] = b0.x; c2A[1] = b0.y; c2A[2] = b1.x; c2A[3] = b1.y;
            c2B[0] = b0.x; c2B[1] = b0.y; c2B[2] = b1.x; c2B[3] = b1.y;
        }
        #pragma unroll
        for (int i = 0; i < 16; i++) {
            u64 biA = pack2(t1A[i]), biB = pack2(t1B[i]);
            ulonglong2 w0 = s_w2v[i * 2], w1r = s_w2v[i * 2 + 1];
            c2A[0] = fma2(biA, w0.x, c2A[0]); c2A[1] = fma2(biA, w0.y, c2A[1]);
            c2A[2] = fma2(biA, w1r.x, c2A[2]); c2A[3] = fma2(biA, w1r.y, c2A[3]);
            c2B[0] = fma2(biB, w0.x, c2B[0]); c2B[1] = fma2(biB, w0.y, c2B[1]);
            c2B[2] = fma2(biB, w1r.x, c2B[2]); c2B[3] = fma2(biB, w1r.y, c2B[3]);
        }
        float t2A[8], t2B[8];
        #pragma unroll
        for (int p = 0; p < 4; p++) {
            float lo, hi;
            unpack2(c2A[p], lo, hi); t2A[2 * p] = fmaxf(lo, 0.f); t2A[2 * p + 1] = fmaxf(hi, 0.f);
            unpack2(c2B[p], lo, hi); t2B[2 * p] = fmaxf(lo, 0.f); t2B[2 * p + 1] = fmaxf(hi, 0.f);
        }

        // layer 3: 8 -> 4
        u64 c3A0, c3A1, c3B0, c3B1;
        {
            ulonglong2 b = s_b3v[0];
            c3A0 = b.x; c3A1 = b.y; c3B0 = b.x; c3B1 = b.y;
        }
        #pragma unroll
        for (int i = 0; i < 8; i++) {
            u64 biA = pack2(t2A[i]), biB = pack2(t2B[i]);
            ulonglong2 w = s_w3v[i];
            c3A0 = fma2(biA, w.x, c3A0); c3A1 = fma2(biA, w.y, c3A1);
            c3B0 = fma2(biB, w.x, c3B0); c3B1 = fma2(biB, w.y, c3B1);
        }
        float e0A, e1A, e2A, e3A, e0B, e1B, e2B, e3B;
        unpack2(c3A0, e0A, e1A); unpack2(c3A1, e2A, e3A);
        unpack2(c3B0, e0B, e1B); unpack2(c3B1, e2B, e3B);

        // log_softmax per edge
        {
            float mx = fmaxf(fmaxf(e0A, e1A), fmaxf(e2A, e3A));
            float x0 = __expf(e0A - mx), x1 = __expf(e1A - mx), x2 = __expf(e2A - mx), x3 = __expf(e3A - mx);
            float lse = mx + __logf(x0 + x1 + x2 + x3);
            reinterpret_cast<float4*>(out_e)[eA] = make_float4(e0A - lse, e1A - lse, e2A - lse, e3A - lse);
        }
        {
            float mx = fmaxf(fmaxf(e0B, e1B), fmaxf(e2B, e3B));
            float x0 = __expf(e0B - mx), x1 = __expf(e1B - mx), x2 = __expf(e2B - mx), x3 = __expf(e3B - mx);
            float lse = mx + __logf(x0 + x1 + x2 + x3);
            reinterpret_cast<float4*>(out_e)[eB] = make_float4(e0B - lse, e1B - lse, e2B - lse, e3B - lse);
        }

        // layer-2 attention scatter
        {
            float alpha = sdA.z + ald2A + e0A * s_c2[0] + e1A * s_c2[1] + e2A * s_c2[2] + e3A * s_c2[3];
            float ex2 = __expf(leaky(alpha));
            red_v4(g_acc2 + (size_t)dA * 4, ex2 * sdA.x, ex2 * sdA.y, ex2, 0.f);
        }
        {
            float alpha = sdB.z + ald2B + e0B * s_c2[0] + e1B * s_c2[1] + e2B * s_c2[2] + e3B * s_c2[3];
            float ex2 = __expf(leaky(alpha));
            red_v4(g_acc2 + (size_t)dB * 4, ex2 * sdB.x, ex2 * sdB.y, ex2, 0.f);
        }

        // accumulate e-sums locally across chunks
        esum0 += e0A + e0B;
        esum1 += e1A + e1B;
        esum2 += e2A + e2B;
        esum3 += e3A + e3B;

        __syncthreads();  // protect s_t0 reuse next chunk
    }

    // per-warp e-sum -> distributed partials (once per CTA)
    #pragma unroll
    for (int o = 16; o > 0; o >>= 1) {
        esum0 += __shfl_down_sync(0xffffffffu, esum0, o);
        esum1 += __shfl_down_sync(0xffffffffu, esum1, o);
        esum2 += __shfl_down_sync(0xffffffffu, esum2, o);
        esum3 += __shfl_down_sync(0xffffffffu, esum3, o);
    }
    if ((t & 31) == 0) {
        int slot = (blockIdx.x * 8 + (t >> 5)) & 255;
        red_v4(g_esum_part + slot * 4, esum0, esum1, esum2, esum3);
    }
}

// ---------------- K5: finalize layer 2 + node log_softmax (inline esum reduce) ----------------
__global__ void __launch_bounds__(256) k_node3(const float* __restrict__ b2,
                                               float* __restrict__ out_n) {
    __shared__ float4 redsh[8];
    int t = threadIdx.x;
    {
        float4 v = reinterpret_cast<const float4*>(g_esum_part)[t];
        #pragma unroll
        for (int o = 16; o > 0; o >>= 1) {
            v.x += __shfl_down_sync(0xffffffffu, v.x, o);
            v.y += __shfl_down_sync(0xffffffffu, v.y, o);
            v.z += __shfl_down_sync(0xffffffffu, v.z, o);
            v.w += __shfl_down_sync(0xffffffffu, v.w, o);
        }
        if ((t & 31) == 0) redsh[t >> 5] = v;
    }
    __syncthreads();
    float es0, es1, es2, es3;
    {
        float4 r = redsh[0];
        #pragma unroll
        for (int i = 1; i < 8; i++) { r.x += redsh[i].x; r.y += redsh[i].y; r.z += redsh[i].z; r.w += redsh[i].w; }
        es0 = r.x; es1 = r.y; es2 = r.z; es3 = r.w;
    }
    int n = blockIdx.x * 256 + t;
    if (n >= NN) return;
    const float invE = 1.f / (float)EE;
    float4 sd = reinterpret_cast<const float4*>(g_sd2)[n];  // {h20,h21,al2s,al2d}
    float a = sd.z + sd.w + invE * (es0 * g_c2[0] + es1 * g_c2[1] + es2 * g_c2[2] + es3 * g_c2[3]);
    float ex = __expf(leaky(a));
    float4 acc = reinterpret_cast<const float4*>(g_acc2)[n];
    float den = 1.f / (acc.z + ex + 1e-16f);
    float o0 = (acc.x + ex * sd.x) * den + b2[0];
    float o1 = (acc.y + ex * sd.y) * den + b2[1];
    float m = fmaxf(o0, o1);
    float l = m + __logf(__expf(o0 - m) + __expf(o1 - m));
    reinterpret_cast<float2*>(out_n)[n] = make_float2(o0 - l, o1 - l);
}

// ---------------- launch ----------------
extern "C" void kernel_launch(void* const* d_in, const int* in_sizes, int n_in,
                              void* d_out, int out_size) {
    const float* x   = (const float*)d_in[0];
    const float* ea  = (const float*)d_in[1];
    const float* W1  = (const float*)d_in[2];
    const float* as1 = (const float*)d_in[3];
    const float* ad1 = (const float*)d_in[4];
    const float* We1 = (const float*)d_in[5];
    const float* ae1 = (const float*)d_in[6];
    const float* b1  = (const float*)d_in[7];
    const float* mw0 = (const float*)d_in[8];
    const float* mb0 = (const float*)d_in[9];
    const float* mw1 = (const float*)d_in[10];
    const float* mb1 = (const float*)d_in[11];
    const float* mw2 = (const float*)d_in[12];
    const float* mb2 = (const float*)d_in[13];
    const float* mw3 = (const float*)d_in[14];
    const float* mb3 = (const float*)d_in[15];
    const float* W2  = (const float*)d_in[16];
    const float* as2 = (const float*)d_in[17];
    const float* ad2 = (const float*)d_in[18];
    const float* We2 = (const float*)d_in[19];
    const float* ae2 = (const float*)d_in[20];
    const float* b2  = (const float*)d_in[21];
    const int* ei    = (const int*)d_in[22];
    const int* srcp = ei;
    const int* dstp = ei + EE;
    float* out = (float*)d_out;

    k_node1<<<(NN + 255) / 256, 256>>>(W1, as1, ad1, We1, ae1, We2, ae2);
    k_edge1<<<EE / 256, 256>>>(srcp, dstp, ea, x);
    k_node2<<<(NN + 255) / 256, 256>>>(x, W1, b1, mw0, W2, as2, ad2);
    k_edge2<<<PGRID, 256>>>(srcp, dstp, ea, mw0, mb0, mw1, mb1, mw2, mb2, mw3, mb3,
                            out + 2 * NN);
    k_node3<<<(NN + 255) / 256, 256>>>(b2, out);
}

// round 16
// speedup vs baseline: 1.0397x; 1.0397x over previous
#include <cuda_runtime.h>

#define NN 100000
#define EE 3200000

typedef unsigned long long u64;

// ---------------- scratch (device globals; no dynamic allocation) ----------------
// per-node dest record: {acc0..3, denom, pad...}  (32B)
__device__ __align__(128) float g_dr[NN * 8];
__device__ __align__(16) float g_acc2[NN * 4];    // layer2: {sum ex*h20, sum ex*h21, sum ex, pad}
__device__ __align__(128) float g_psrc[NN * 16];  // h1 @ mw0[0:16]   (64B records)
__device__ __align__(128) float g_pdst[NN * 16];  // h1 @ mw0[19:35]  (64B records)
__device__ __align__(16) float g_sd2[NN * 4];     // {h20, h21, al2s, al2d}
__device__ __align__(16) float g_easum_part[256 * 4];
__device__ __align__(16) float g_esum_part[256 * 4];
__device__ __align__(16) float g_c1[4];           // We1 @ ae1
__device__ __align__(16) float g_c2[4];           // We2 @ ae2
__device__ __align__(16) float g_wal[4];          // W1 @ as1
__device__ __align__(16) float g_wad[4];          // W1 @ ad1

// ---------------- helpers ----------------
__device__ __forceinline__ float leaky(float x) { return x > 0.f ? x : 0.2f * x; }

__device__ __forceinline__ u64 pack2(float x) {
    u64 r; asm("mov.b64 %0, {%1, %1};" : "=l"(r) : "f"(x)); return r;
}
__device__ __forceinline__ u64 fma2(u64 a, u64 b, u64 c) {
    u64 d; asm("fma.rn.f32x2 %0, %1, %2, %3;" : "=l"(d) : "l"(a), "l"(b), "l"(c)); return d;
}
__device__ __forceinline__ void unpack2(u64 a, float& x, float& y) {
    asm("mov.b64 {%0, %1}, %2;" : "=f"(x), "=f"(y) : "l"(a));
}
__device__ __forceinline__ void red_v4(float* p, float a, float b, float c, float d) {
    asm volatile("red.global.add.v4.f32 [%0], {%1, %2, %3, %4};"
                 :: "l"(p), "f"(a), "f"(b), "f"(c), "f"(d) : "memory");
}
__device__ __forceinline__ void red_f32(float* p, float v) {
    asm volatile("red.global.add.f32 [%0], %1;" :: "l"(p), "f"(v) : "memory");
}

// ---------------- K1: zero accumulators + constants (block 0) ----------------
__global__ void __launch_bounds__(256) k_node1(const float* __restrict__ W1,
                                               const float* __restrict__ as1,
                                               const float* __restrict__ ad1,
                                               const float* __restrict__ We1,
                                               const float* __restrict__ ae1,
                                               const float* __restrict__ We2,
                                               const float* __restrict__ ae2) {
    int t = threadIdx.x;
    if (blockIdx.x == 0) {
        if (t < 3) {
            float s = 0.f;
            #pragma unroll
            for (int k = 0; k < 16; k++) s += We1[t * 16 + k] * ae1[k];
            g_c1[t] = s;
        }
        if (t == 3) g_c1[3] = 0.f;
        if (t >= 4 && t < 8) {
            int j = t - 4;
            g_c2[j] = We2[j * 2] * ae2[0] + We2[j * 2 + 1] * ae2[1];
        }
        if (t >= 8 && t < 12) {
            int j = t - 8;
            float sA = 0.f, sD = 0.f;
            #pragma unroll
            for (int k = 0; k < 16; k++) {
                sA += W1[j * 16 + k] * as1[k];
                sD += W1[j * 16 + k] * ad1[k];
            }
            g_wal[j] = sA;
            g_wad[j] = sD;
        }
    }
    int n = blockIdx.x * 256 + t;
    float4 z = make_float4(0.f, 0.f, 0.f, 0.f);
    if (n < 256) {
        reinterpret_cast<float4*>(g_easum_part)[n] = z;
        reinterpret_cast<float4*>(g_esum_part)[n] = z;
    }
    if (n >= NN) return;
    reinterpret_cast<float4*>(g_dr)[n * 2] = z;
    reinterpret_cast<float4*>(g_dr)[n * 2 + 1] = z;
    reinterpret_cast<float4*>(g_acc2)[n] = z;
}

// ---------------- K2: layer-1 edge pass (scatter ex*x[s]) + warp-level ea sums ----------------
__global__ void __launch_bounds__(256) k_edge1(const int* __restrict__ src,
                                               const int* __restrict__ dst,
                                               const float* __restrict__ ea,
                                               const float* __restrict__ x) {
    int t = threadIdx.x;
    int e = blockIdx.x * 256 + t;  // grid covers EE exactly
    int s = src[e], d = dst[e];
    float ea0 = ea[e * 3], ea1 = ea[e * 3 + 1], ea2 = ea[e * 3 + 2];
    float4 xs = reinterpret_cast<const float4*>(x)[s];
    float4 xd = reinterpret_cast<const float4*>(x)[d];
    float4 wl = *reinterpret_cast<const float4*>(g_wal);
    float4 wd = *reinterpret_cast<const float4*>(g_wad);
    float4 c1 = *reinterpret_cast<const float4*>(g_c1);
    float als = xs.x * wl.x + xs.y * wl.y + xs.z * wl.z + xs.w * wl.w;
    float ald = xd.x * wd.x + xd.y * wd.y + xd.z * wd.z + xd.w * wd.w;
    float a = als + ald + ea0 * c1.x + ea1 * c1.y + ea2 * c1.z;
    float ex = __expf(leaky(a));
    float* dr = g_dr + (size_t)d * 8;
    red_v4(dr, ex * xs.x, ex * xs.y, ex * xs.z, ex * xs.w);
    red_f32(dr + 4, ex);

    // per-warp edge_attr sum -> distributed partials (no barrier)
    float s0 = ea0, s1 = ea1, s2 = ea2;
    #pragma unroll
    for (int o = 16; o > 0; o >>= 1) {
        s0 += __shfl_down_sync(0xffffffffu, s0, o);
        s1 += __shfl_down_sync(0xffffffffu, s1, o);
        s2 += __shfl_down_sync(0xffffffffu, s2, o);
    }
    if ((t & 31) == 0) {
        int slot = (blockIdx.x * 8 + (t >> 5)) & 255;
        red_v4(g_easum_part + slot * 4, s0, s1, s2, 0.f);
    }
}

// ---------------- K3: finalize layer 1 + derive per-node layer-2 quantities ----------------
__global__ void __launch_bounds__(256) k_node2(const float* __restrict__ x,
                                               const float* __restrict__ W1,
                                               const float* __restrict__ b1,
                                               const float* __restrict__ mw0,
                                               const float* __restrict__ W2,
                                               const float* __restrict__ as2,
                                               const float* __restrict__ ad2) {
    __shared__ float sws[256];  // mw0 rows 0..15
    __shared__ float swd[256];  // mw0 rows 19..34
    __shared__ float sW1[64], sb1[16], sW2[32], sas2[2], sad2[2];
    __shared__ float4 redsh[8];
    int t = threadIdx.x;
    // inline easum reduce (all blocks, redundant, cheap)
    {
        float4 v = reinterpret_cast<const float4*>(g_easum_part)[t];
        #pragma unroll
        for (int o = 16; o > 0; o >>= 1) {
            v.x += __shfl_down_sync(0xffffffffu, v.x, o);
            v.y += __shfl_down_sync(0xffffffffu, v.y, o);
            v.z += __shfl_down_sync(0xffffffffu, v.z, o);
        }
        if ((t & 31) == 0) redsh[t >> 5] = v;
    }
    sws[t] = mw0[t];
    swd[t] = mw0[19 * 16 + t];
    if (t < 64) sW1[t] = W1[t];
    if (t >= 64 && t < 80) sb1[t - 64] = b1[t - 64];
    if (t >= 80 && t < 112) sW2[t - 80] = W2[t - 80];
    if (t >= 112 && t < 114) sas2[t - 112] = as2[t - 112];
    if (t >= 114 && t < 116) sad2[t - 114] = ad2[t - 114];
    __syncthreads();
    float m0, m1, m2;
    {
        float4 r = redsh[0];
        #pragma unroll
        for (int i = 1; i < 8; i++) { r.x += redsh[i].x; r.y += redsh[i].y; r.z += redsh[i].z; }
        const float invE = 1.f / (float)EE;
        m0 = r.x * invE; m1 = r.y * invE; m2 = r.z * invE;
    }
    int n = blockIdx.x * 256 + t;
    if (n >= NN) return;

    float4 xv = reinterpret_cast<const float4*>(x)[n];
    float4 wl = *reinterpret_cast<const float4*>(g_wal);
    float4 wd = *reinterpret_cast<const float4*>(g_wad);
    float als = xv.x * wl.x + xv.y * wl.y + xv.z * wl.z + xv.w * wl.w;
    float ald = xv.x * wd.x + xv.y * wd.y + xv.z * wd.z + xv.w * wd.w;
    float aself = leaky(als + ald + m0 * g_c1[0] + m1 * g_c1[1] + m2 * g_c1[2]);
    float ex = __expf(aself);
    const float* dr = g_dr + (size_t)n * 8;
    float inv = 1.f / (dr[4] + ex + 1e-16f);

    float4 acc = *reinterpret_cast<const float4*>(dr);
    acc.x += ex * xv.x;
    acc.y += ex * xv.y;
    acc.z += ex * xv.z;
    acc.w += ex * xv.w;

    float h1[16];
    #pragma unroll
    for (int j = 0; j < 16; j++) {
        float h = acc.x * sW1[j] + acc.y * sW1[16 + j] + acc.z * sW1[32 + j] + acc.w * sW1[48 + j];
        h1[j] = h * inv + sb1[j];
    }

    float ps[16], pd[16];
    #pragma unroll
    for (int j = 0; j < 16; j++) {
        float a0 = 0.f, a1 = 0.f;
        #pragma unroll
        for (int i = 0; i < 16; i++) {
            a0 += h1[i] * sws[i * 16 + j];
            a1 += h1[i] * swd[i * 16 + j];
        }
        ps[j] = a0;
        pd[j] = a1;
    }
    float h20 = 0.f, h21 = 0.f;
    #pragma unroll
    for (int i = 0; i < 16; i++) {
        h20 += h1[i] * sW2[i * 2];
        h21 += h1[i] * sW2[i * 2 + 1];
    }
    float al2s = h20 * sas2[0] + h21 * sas2[1];
    float al2d = h20 * sad2[0] + h21 * sad2[1];

    float4* pp = reinterpret_cast<float4*>(g_psrc + (size_t)n * 16);
    #pragma unroll
    for (int q = 0; q < 4; q++)
        pp[q] = make_float4(ps[4 * q], ps[4 * q + 1], ps[4 * q + 2], ps[4 * q + 3]);
    float4* pq = reinterpret_cast<float4*>(g_pdst + (size_t)n * 16);
    #pragma unroll
    for (int q = 0; q < 4; q++)
        pq[q] = make_float4(pd[4 * q], pd[4 * q + 1], pd[4 * q + 2], pd[4 * q + 3]);
    reinterpret_cast<float4*>(g_sd2)[n] = make_float4(h20, h21, al2s, al2d);
}

// ---------------- K4: edge MLP, two-phase cooperative gather (no swizzle) ----------------
#define EPB 512
__global__ void __launch_bounds__(256) k_edge2(const int* __restrict__ src,
                                               const int* __restrict__ dst,
                                               const float* __restrict__ ea,
                                               const float* __restrict__ mw0,
                                               const float* __restrict__ mb0,
                                               const float* __restrict__ mw1,
                                               const float* __restrict__ mb1,
                                               const float* __restrict__ mw2,
                                               const float* __restrict__ mb2,
                                               const float* __restrict__ mw3,
                                               const float* __restrict__ mb3,
                                               float* __restrict__ out_e) {
    __shared__ __align__(16) float4 s_w0q[12];      // mw0 rows 16..18, by quarter
    __shared__ __align__(16) float4 s_b0q[4];
    __shared__ __align__(16) ulonglong2 s_w1v[64];
    __shared__ __align__(16) ulonglong2 s_b1v[4];
    __shared__ __align__(16) ulonglong2 s_w2v[32];
    __shared__ __align__(16) ulonglong2 s_b2v[2];
    __shared__ __align__(16) ulonglong2 s_w3v[8];
    __shared__ __align__(16) ulonglong2 s_b3v[1];
    __shared__ float s_c2[4];
    __shared__ __align__(16) float s_t0[EPB * 20];  // staged t0, 80B stride (16B aligned)
    __shared__ int s_sidx[EPB];
    __shared__ int s_didx[EPB];

    int t = threadIdx.x;
    if (t < 12) s_w0q[t] = reinterpret_cast<const float4*>(mw0)[64 + t];
    else if (t < 16) s_b0q[t - 12] = reinterpret_cast<const float4*>(mb0)[t - 12];
    else if (t < 80) s_w1v[t - 16] = reinterpret_cast<const ulonglong2*>(mw1)[t - 16];
    else if (t < 84) s_b1v[t - 80] = reinterpret_cast<const ulonglong2*>(mb1)[t - 80];
    else if (t < 116) s_w2v[t - 84] = reinterpret_cast<const ulonglong2*>(mw2)[t - 84];
    else if (t < 118) s_b2v[t - 116] = reinterpret_cast<const ulonglong2*>(mb2)[t - 116];
    else if (t < 126) s_w3v[t - 118] = reinterpret_cast<const ulonglong2*>(mw3)[t - 118];
    else if (t < 127) s_b3v[0] = reinterpret_cast<const ulonglong2*>(mb3)[0];
    if (t >= 128 && t < 132) s_c2[t - 128] = g_c2[t - 128];
    __syncthreads();

    int ebase = blockIdx.x * EPB;

    // ---- phase 1: cooperative gather (4 lanes per edge, 64 edges/pass) + layer 0 ----
    {
        int q = t & 3;
        int er = t >> 2;  // 0..63
        float4 w0a = s_w0q[q], w0b = s_w0q[4 + q], w0c = s_w0q[8 + q], b0 = s_b0q[q];
        #pragma unroll
        for (int k = 0; k < 8; k++) {
            int el = k * 64 + er;
            int e = ebase + el;
            int s = src[e], d = dst[e];
            float ea0 = ea[e * 3], ea1 = ea[e * 3 + 1], ea2 = ea[e * 3 + 2];
            float4 ps = *reinterpret_cast<const float4*>(g_psrc + (size_t)s * 16 + q * 4);
            float4 pd = *reinterpret_cast<const float4*>(g_pdst + (size_t)d * 16 + q * 4);
            float4 v;
            v.x = fmaxf(ps.x + pd.x + b0.x + ea0 * w0a.x + ea1 * w0b.x + ea2 * w0c.x, 0.f);
            v.y = fmaxf(ps.y + pd.y + b0.y + ea0 * w0a.y + ea1 * w0b.y + ea2 * w0c.y, 0.f);
            v.z = fmaxf(ps.z + pd.z + b0.z + ea0 * w0a.z + ea1 * w0b.z + ea2 * w0c.z, 0.f);
            v.w = fmaxf(ps.w + pd.w + b0.w + ea0 * w0a.w + ea1 * w0b.w + ea2 * w0c.w, 0.f);
            *reinterpret_cast<float4*>(s_t0 + el * 20 + q * 4) = v;
            if (q == 0) {
                // register-sourced index staging (no extra loads)
                s_sidx[el] = s;
                s_didx[el] = d;
            }
        }
    }
    __syncthreads();

    // ---- phase 2: layers 1-3 for 2 edges/thread ----
    int eA = ebase + t;
    int eB = eA + 256;
    float t0A[16], t0B[16];
    {
        const float4* pA = reinterpret_cast<const float4*>(s_t0 + t * 20);
        const float4* pB = reinterpret_cast<const float4*>(s_t0 + (t + 256) * 20);
        #pragma unroll
        for (int qq = 0; qq < 4; qq++) {
            float4 a = pA[qq], b = pB[qq];
            t0A[4 * qq] = a.x; t0A[4 * qq + 1] = a.y; t0A[4 * qq + 2] = a.z; t0A[4 * qq + 3] = a.w;
            t0B[4 * qq] = b.x; t0B[4 * qq + 1] = b.y; t0B[4 * qq + 2] = b.z; t0B[4 * qq + 3] = b.w;
        }
    }
    int sA = s_sidx[t], dA = s_didx[t];
    int sB = s_sidx[t + 256], dB = s_didx[t + 256];
    float4 sdA = reinterpret_cast<const float4*>(g_sd2)[sA];  // {h20,h21,al2s,al2d}
    float4 sdB = reinterpret_cast<const float4*>(g_sd2)[sB];
    float ald2A = g_sd2[(size_t)dA * 4 + 3];
    float ald2B = g_sd2[(size_t)dB * 4 + 3];

    // layer 1: 16 -> 16
    u64 accA[8], accB[8];
    #pragma unroll
    for (int qq = 0; qq < 4; qq++) {
        ulonglong2 b = s_b1v[qq];
        accA[2 * qq] = b.x; accA[2 * qq + 1] = b.y;
        accB[2 * qq] = b.x; accB[2 * qq + 1] = b.y;
    }
    #pragma unroll
    for (int i = 0; i < 16; i++) {
        u64 biA = pack2(t0A[i]), biB = pack2(t0B[i]);
        #pragma unroll
        for (int qq = 0; qq < 4; qq++) {
            ulonglong2 w = s_w1v[i * 4 + qq];
            accA[2 * qq] = fma2(biA, w.x, accA[2 * qq]);
            accA[2 * qq + 1] = fma2(biA, w.y, accA[2 * qq + 1]);
            accB[2 * qq] = fma2(biB, w.x, accB[2 * qq]);
            accB[2 * qq + 1] = fma2(biB, w.y, accB[2 * qq + 1]);
        }
    }
    float t1A[16], t1B[16];
    #pragma unroll
    for (int p = 0; p < 8; p++) {
        float lo, hi;
        unpack2(accA[p], lo, hi); t1A[2 * p] = fmaxf(lo, 0.f); t1A[2 * p + 1] = fmaxf(hi, 0.f);
        unpack2(accB[p], lo, hi); t1B[2 * p] = fmaxf(lo, 0.f); t1B[2 * p + 1] = fmaxf(hi, 0.f);
    }

    // layer 2: 16 -> 8
    u64 c2A[4], c2B[4];
    {
        ulonglong2 b0 = s_b2v[0], b1 = s_b2v[1];
        c2A[0] = b0.x; c2A[1] = b0.y; c2A[2] = b1.x; c2A[3] = b1.y;
        c2B[0] = b0.x; c2B[1] = b0.y; c2B[2] = b1.x; c2B[3] = b1.y;
    }
    #pragma unroll
    for (int i = 0; i < 16; i++) {
        u64 biA = pack2(t1A[i]), biB = pack2(t1B[i]);
        ulonglong2 w0 = s_w2v[i * 2], w1r = s_w2v[i * 2 + 1];
        c2A[0] = fma2(biA, w0.x, c2A[0]); c2A[1] = fma2(biA, w0.y, c2A[1]);
        c2A[2] = fma2(biA, w1r.x, c2A[2]); c2A[3] = fma2(biA, w1r.y, c2A[3]);
        c2B[0] = fma2(biB, w0.x, c2B[0]); c2B[1] = fma2(biB, w0.y, c2B[1]);
        c2B[2] = fma2(biB, w1r.x, c2B[2]); c2B[3] = fma2(biB, w1r.y, c2B[3]);
    }
    float t2A[8], t2B[8];
    #pragma unroll
    for (int p = 0; p < 4; p++) {
        float lo, hi;
        unpack2(c2A[p], lo, hi); t2A[2 * p] = fmaxf(lo, 0.f); t2A[2 * p + 1] = fmaxf(hi, 0.f);
        unpack2(c2B[p], lo, hi); t2B[2 * p] = fmaxf(lo, 0.f); t2B[2 * p + 1] = fmaxf(hi, 0.f);
    }

    // layer 3: 8 -> 4
    u64 c3A0, c3A1, c3B0, c3B1;
    {
        ulonglong2 b = s_b3v[0];
        c3A0 = b.x; c3A1 = b.y; c3B0 = b.x; c3B1 = b.y;
    }
    #pragma unroll
    for (int i = 0; i < 8; i++) {
        u64 biA = pack2(t2A[i]), biB = pack2(t2B[i]);
        ulonglong2 w = s_w3v[i];
        c3A0 = fma2(biA, w.x, c3A0); c3A1 = fma2(biA, w.y, c3A1);
        c3B0 = fma2(biB, w.x, c3B0); c3B1 = fma2(biB, w.y, c3B1);
    }
    float e0A, e1A, e2A, e3A, e0B, e1B, e2B, e3B;
    unpack2(c3A0, e0A, e1A); unpack2(c3A1, e2A, e3A);
    unpack2(c3B0, e0B, e1B); unpack2(c3B1, e2B, e3B);

    // log_softmax per edge
    {
        float mx = fmaxf(fmaxf(e0A, e1A), fmaxf(e2A, e3A));
        float x0 = __expf(e0A - mx), x1 = __expf(e1A - mx), x2 = __expf(e2A - mx), x3 = __expf(e3A - mx);
        float lse = mx + __logf(x0 + x1 + x2 + x3);
        reinterpret_cast<float4*>(out_e)[eA] = make_float4(e0A - lse, e1A - lse, e2A - lse, e3A - lse);
    }
    {
        float mx = fmaxf(fmaxf(e0B, e1B), fmaxf(e2B, e3B));
        float x0 = __expf(e0B - mx), x1 = __expf(e1B - mx), x2 = __expf(e2B - mx), x3 = __expf(e3B - mx);
        float lse = mx + __logf(x0 + x1 + x2 + x3);
        reinterpret_cast<float4*>(out_e)[eB] = make_float4(e0B - lse, e1B - lse, e2B - lse, e3B - lse);
    }

    // layer-2 attention scatter
    {
        float alpha = sdA.z + ald2A + e0A * s_c2[0] + e1A * s_c2[1] + e2A * s_c2[2] + e3A * s_c2[3];
        float ex2 = __expf(leaky(alpha));
        red_v4(g_acc2 + (size_t)dA * 4, ex2 * sdA.x, ex2 * sdA.y, ex2, 0.f);
    }
    {
        float alpha = sdB.z + ald2B + e0B * s_c2[0] + e1B * s_c2[1] + e2B * s_c2[2] + e3B * s_c2[3];
        float ex2 = __expf(leaky(alpha));
        red_v4(g_acc2 + (size_t)dB * 4, ex2 * sdB.x, ex2 * sdB.y, ex2, 0.f);
    }

    // per-warp e-sum -> distributed partials (no barrier)
    float r0 = e0A + e0B, r1 = e1A + e1B, r2 = e2A + e2B, r3 = e3A + e3B;
    #pragma unroll
    for (int o = 16; o > 0; o >>= 1) {
        r0 += __shfl_down_sync(0xffffffffu, r0, o);
        r1 += __shfl_down_sync(0xffffffffu, r1, o);
        r2 += __shfl_down_sync(0xffffffffu, r2, o);
        r3 += __shfl_down_sync(0xffffffffu, r3, o);
    }
    if ((t & 31) == 0) {
        int slot = (blockIdx.x * 8 + (t >> 5)) & 255;
        red_v4(g_esum_part + slot * 4, r0, r1, r2, r3);
    }
}

// ---------------- K5: finalize layer 2 + node log_softmax (inline esum reduce) ----------------
__global__ void __launch_bounds__(256) k_node3(const float* __restrict__ b2,
                                               float* __restrict__ out_n) {
    __shared__ float4 redsh[8];
    int t = threadIdx.x;
    {
        float4 v = reinterpret_cast<const float4*>(g_esum_part)[t];
        #pragma unroll
        for (int o = 16; o > 0; o >>= 1) {
            v.x += __shfl_down_sync(0xffffffffu, v.x, o);
            v.y += __shfl_down_sync(0xffffffffu, v.y, o);
            v.z += __shfl_down_sync(0xffffffffu, v.z, o);
            v.w += __shfl_down_sync(0xffffffffu, v.w, o);
        }
        if ((t & 31) == 0) redsh[t >> 5] = v;
    }
    __syncthreads();
    float es0, es1, es2, es3;
    {
        float4 r = redsh[0];
        #pragma unroll
        for (int i = 1; i < 8; i++) { r.x += redsh[i].x; r.y += redsh[i].y; r.z += redsh[i].z; r.w += redsh[i].w; }
        es0 = r.x; es1 = r.y; es2 = r.z; es3 = r.w;
    }
    int n = blockIdx.x * 256 + t;
    if (n >= NN) return;
    const float invE = 1.f / (float)EE;
    float4 sd = reinterpret_cast<const float4*>(g_sd2)[n];  // {h20,h21,al2s,al2d}
    float a = sd.z + sd.w + invE * (es0 * g_c2[0] + es1 * g_c2[1] + es2 * g_c2[2] + es3 * g_c2[3]);
    float ex = __expf(leaky(a));
    float4 acc = reinterpret_cast<const float4*>(g_acc2)[n];
    float den = 1.f / (acc.z + ex + 1e-16f);
    float o0 = (acc.x + ex * sd.x) * den + b2[0];
    float o1 = (acc.y + ex * sd.y) * den + b2[1];
    float m = fmaxf(o0, o1);
    float l = m + __logf(__expf(o0 - m) + __expf(o1 - m));
    reinterpret_cast<float2*>(out_n)[n] = make_float2(o0 - l, o1 - l);
}

// ---------------- launch ----------------
extern "C" void kernel_launch(void* const* d_in, const int* in_sizes, int n_in,
                              void* d_out, int out_size) {
    const float* x   = (const float*)d_in[0];
    const float* ea  = (const float*)d_in[1];
    const float* W1  = (const float*)d_in[2];
    const float* as1 = (const float*)d_in[3];
    const float* ad1 = (const float*)d_in[4];
    const float* We1 = (const float*)d_in[5];
    const float* ae1 = (const float*)d_in[6];
    const float* b1  = (const float*)d_in[7];
    const float* mw0 = (const float*)d_in[8];
    const float* mb0 = (const float*)d_in[9];
    const float* mw1 = (const float*)d_in[10];
    const float* mb1 = (const float*)d_in[11];
    const float* mw2 = (const float*)d_in[12];
    const float* mb2 = (const float*)d_in[13];
    const float* mw3 = (const float*)d_in[14];
    const float* mb3 = (const float*)d_in[15];
    const float* W2  = (const float*)d_in[16];
    const float* as2 = (const float*)d_in[17];
    const float* ad2 = (const float*)d_in[18];
    const float* We2 = (const float*)d_in[19];
    const float* ae2 = (const float*)d_in[20];
    const float* b2  = (const float*)d_in[21];
    const int* ei    = (const int*)d_in[22];
    const int* srcp = ei;
    const int* dstp = ei + EE;
    float* out = (float*)d_out;

    k_node1<<<(NN + 255) / 256, 256>>>(W1, as1, ad1, We1, ae1, We2, ae2);
    k_edge1<<<EE / 256, 256>>>(srcp, dstp, ea, x);
    k_node2<<<(NN + 255) / 256, 256>>>(x, W1, b1, mw0, W2, as2, ad2);
    k_edge2<<<EE / EPB, 256>>>(srcp, dstp, ea, mw0, mb0, mw1, mb1, mw2, mb2, mw3, mb3,
                               out + 2 * NN);
    k_node3<<<(NN + 255) / 256, 256>>>(b2, out);
}

// round 17
// speedup vs baseline: 1.0510x; 1.0108x over previous
#include <cuda_runtime.h>

#define NN 100000
#define EE 3200000

typedef unsigned long long u64;

// ---------------- scratch (device globals; no dynamic allocation) ----------------
// per-node dest record: {acc0..3, denom, pad...}  (32B)
__device__ __align__(128) float g_dr[NN * 8];
__device__ __align__(16) float g_acc2[NN * 4];    // layer2: {sum ex*h20, sum ex*h21, sum ex, pad}
__device__ __align__(128) float g_psrc[NN * 16];  // h1 @ mw0[0:16]   (64B records)
__device__ __align__(128) float g_pdst[NN * 16];  // h1 @ mw0[19:35]  (64B records)
__device__ __align__(16) float g_sd2[NN * 4];     // {h20, h21, al2s, al2d}
__device__ __align__(16) float g_easum_part[256 * 4];
__device__ __align__(16) float g_esum_part[256 * 4];
__device__ __align__(16) float g_c1[4];           // We1 @ ae1
__device__ __align__(16) float g_c2[4];           // We2 @ ae2
__device__ __align__(16) float g_wal[4];          // W1 @ as1
__device__ __align__(16) float g_wad[4];          // W1 @ ad1

// ---------------- helpers ----------------
__device__ __forceinline__ float leaky(float x) { return x > 0.f ? x : 0.2f * x; }

__device__ __forceinline__ u64 pack2(float x) {
    u64 r; asm("mov.b64 %0, {%1, %1};" : "=l"(r) : "f"(x)); return r;
}
__device__ __forceinline__ u64 fma2(u64 a, u64 b, u64 c) {
    u64 d; asm("fma.rn.f32x2 %0, %1, %2, %3;" : "=l"(d) : "l"(a), "l"(b), "l"(c)); return d;
}
__device__ __forceinline__ void unpack2(u64 a, float& x, float& y) {
    asm("mov.b64 {%0, %1}, %2;" : "=f"(x), "=f"(y) : "l"(a));
}
__device__ __forceinline__ void red_v4(float* p, float a, float b, float c, float d) {
    asm volatile("red.global.add.v4.f32 [%0], {%1, %2, %3, %4};"
                 :: "l"(p), "f"(a), "f"(b), "f"(c), "f"(d) : "memory");
}
__device__ __forceinline__ void red_f32(float* p, float v) {
    asm volatile("red.global.add.f32 [%0], %1;" :: "l"(p), "f"(v) : "memory");
}

// ---------------- K1: zero accumulators + constants (block 0) ----------------
__global__ void __launch_bounds__(256) k_node1(const float* __restrict__ W1,
                                               const float* __restrict__ as1,
                                               const float* __restrict__ ad1,
                                               const float* __restrict__ We1,
                                               const float* __restrict__ ae1,
                                               const float* __restrict__ We2,
                                               const float* __restrict__ ae2) {
    int t = threadIdx.x;
    if (blockIdx.x == 0) {
        if (t < 3) {
            float s = 0.f;
            #pragma unroll
            for (int k = 0; k < 16; k++) s += We1[t * 16 + k] * ae1[k];
            g_c1[t] = s;
        }
        if (t == 3) g_c1[3] = 0.f;
        if (t >= 4 && t < 8) {
            int j = t - 4;
            g_c2[j] = We2[j * 2] * ae2[0] + We2[j * 2 + 1] * ae2[1];
        }
        if (t >= 8 && t < 12) {
            int j = t - 8;
            float sA = 0.f, sD = 0.f;
            #pragma unroll
            for (int k = 0; k < 16; k++) {
                sA += W1[j * 16 + k] * as1[k];
                sD += W1[j * 16 + k] * ad1[k];
            }
            g_wal[j] = sA;
            g_wad[j] = sD;
        }
    }
    int n = blockIdx.x * 256 + t;
    float4 z = make_float4(0.f, 0.f, 0.f, 0.f);
    if (n < 256) {
        reinterpret_cast<float4*>(g_easum_part)[n] = z;
        reinterpret_cast<float4*>(g_esum_part)[n] = z;
    }
    if (n >= NN) return;
    reinterpret_cast<float4*>(g_dr)[n * 2] = z;
    reinterpret_cast<float4*>(g_dr)[n * 2 + 1] = z;
    reinterpret_cast<float4*>(g_acc2)[n] = z;
}

// ---------------- K2: layer-1 edge pass, 2 edges/thread (scatter ex*x[s]) ----------------
__global__ void __launch_bounds__(256) k_edge1(const int* __restrict__ src,
                                               const int* __restrict__ dst,
                                               const float* __restrict__ ea,
                                               const float* __restrict__ x) {
    int t = threadIdx.x;
    int e0 = blockIdx.x * 512 + t;   // EE = 6250*512 exactly
    int e1 = e0 + 256;
    int s0 = src[e0], d0 = dst[e0];
    int s1 = src[e1], d1 = dst[e1];
    float ea00 = ea[e0 * 3], ea01 = ea[e0 * 3 + 1], ea02 = ea[e0 * 3 + 2];
    float ea10 = ea[e1 * 3], ea11 = ea[e1 * 3 + 1], ea12 = ea[e1 * 3 + 2];
    float4 xs0 = reinterpret_cast<const float4*>(x)[s0];
    float4 xd0 = reinterpret_cast<const float4*>(x)[d0];
    float4 xs1 = reinterpret_cast<const float4*>(x)[s1];
    float4 xd1 = reinterpret_cast<const float4*>(x)[d1];
    float4 wl = *reinterpret_cast<const float4*>(g_wal);
    float4 wd = *reinterpret_cast<const float4*>(g_wad);
    float4 c1 = *reinterpret_cast<const float4*>(g_c1);
    {
        float als = xs0.x * wl.x + xs0.y * wl.y + xs0.z * wl.z + xs0.w * wl.w;
        float ald = xd0.x * wd.x + xd0.y * wd.y + xd0.z * wd.z + xd0.w * wd.w;
        float a = als + ald + ea00 * c1.x + ea01 * c1.y + ea02 * c1.z;
        float ex = __expf(leaky(a));
        float* dr = g_dr + (size_t)d0 * 8;
        red_v4(dr, ex * xs0.x, ex * xs0.y, ex * xs0.z, ex * xs0.w);
        red_f32(dr + 4, ex);
    }
    {
        float als = xs1.x * wl.x + xs1.y * wl.y + xs1.z * wl.z + xs1.w * wl.w;
        float ald = xd1.x * wd.x + xd1.y * wd.y + xd1.z * wd.z + xd1.w * wd.w;
        float a = als + ald + ea10 * c1.x + ea11 * c1.y + ea12 * c1.z;
        float ex = __expf(leaky(a));
        float* dr = g_dr + (size_t)d1 * 8;
        red_v4(dr, ex * xs1.x, ex * xs1.y, ex * xs1.z, ex * xs1.w);
        red_f32(dr + 4, ex);
    }

    // per-warp edge_attr sum -> distributed partials (no barrier)
    float s0v = ea00 + ea10, s1v = ea01 + ea11, s2v = ea02 + ea12;
    #pragma unroll
    for (int o = 16; o > 0; o >>= 1) {
        s0v += __shfl_down_sync(0xffffffffu, s0v, o);
        s1v += __shfl_down_sync(0xffffffffu, s1v, o);
        s2v += __shfl_down_sync(0xffffffffu, s2v, o);
    }
    if ((t & 31) == 0) {
        int slot = (blockIdx.x * 8 + (t >> 5)) & 255;
        red_v4(g_easum_part + slot * 4, s0v, s1v, s2v, 0.f);
    }
}

// ---------------- K3: finalize layer 1 + derive per-node layer-2 quantities ----------------
__global__ void __launch_bounds__(256) k_node2(const float* __restrict__ x,
                                               const float* __restrict__ W1,
                                               const float* __restrict__ b1,
                                               const float* __restrict__ mw0,
                                               const float* __restrict__ W2,
                                               const float* __restrict__ as2,
                                               const float* __restrict__ ad2) {
    __shared__ float sws[256];  // mw0 rows 0..15
    __shared__ float swd[256];  // mw0 rows 19..34
    __shared__ float sW1[64], sb1[16], sW2[32], sas2[2], sad2[2];
    __shared__ float4 redsh[8];
    int t = threadIdx.x;
    // inline easum reduce (all blocks, redundant, cheap)
    {
        float4 v = reinterpret_cast<const float4*>(g_easum_part)[t];
        #pragma unroll
        for (int o = 16; o > 0; o >>= 1) {
            v.x += __shfl_down_sync(0xffffffffu, v.x, o);
            v.y += __shfl_down_sync(0xffffffffu, v.y, o);
            v.z += __shfl_down_sync(0xffffffffu, v.z, o);
        }
        if ((t & 31) == 0) redsh[t >> 5] = v;
    }
    sws[t] = mw0[t];
    swd[t] = mw0[19 * 16 + t];
    if (t < 64) sW1[t] = W1[t];
    if (t >= 64 && t < 80) sb1[t - 64] = b1[t - 64];
    if (t >= 80 && t < 112) sW2[t - 80] = W2[t - 80];
    if (t >= 112 && t < 114) sas2[t - 112] = as2[t - 112];
    if (t >= 114 && t < 116) sad2[t - 114] = ad2[t - 114];
    __syncthreads();
    float m0, m1, m2;
    {
        float4 r = redsh[0];
        #pragma unroll
        for (int i = 1; i < 8; i++) { r.x += redsh[i].x; r.y += redsh[i].y; r.z += redsh[i].z; }
        const float invE = 1.f / (float)EE;
        m0 = r.x * invE; m1 = r.y * invE; m2 = r.z * invE;
    }
    int n = blockIdx.x * 256 + t;
    if (n >= NN) return;

    float4 xv = reinterpret_cast<const float4*>(x)[n];
    float4 wl = *reinterpret_cast<const float4*>(g_wal);
    float4 wd = *reinterpret_cast<const float4*>(g_wad);
    float als = xv.x * wl.x + xv.y * wl.y + xv.z * wl.z + xv.w * wl.w;
    float ald = xv.x * wd.x + xv.y * wd.y + xv.z * wd.z + xv.w * wd.w;
    float aself = leaky(als + ald + m0 * g_c1[0] + m1 * g_c1[1] + m2 * g_c1[2]);
    float ex = __expf(aself);
    const float* dr = g_dr + (size_t)n * 8;
    float inv = 1.f / (dr[4] + ex + 1e-16f);

    float4 acc = *reinterpret_cast<const float4*>(dr);
    acc.x += ex * xv.x;
    acc.y += ex * xv.y;
    acc.z += ex * xv.z;
    acc.w += ex * xv.w;

    float h1[16];
    #pragma unroll
    for (int j = 0; j < 16; j++) {
        float h = acc.x * sW1[j] + acc.y * sW1[16 + j] + acc.z * sW1[32 + j] + acc.w * sW1[48 + j];
        h1[j] = h * inv + sb1[j];
    }

    float ps[16], pd[16];
    #pragma unroll
    for (int j = 0; j < 16; j++) {
        float a0 = 0.f, a1 = 0.f;
        #pragma unroll
        for (int i = 0; i < 16; i++) {
            a0 += h1[i] * sws[i * 16 + j];
            a1 += h1[i] * swd[i * 16 + j];
        }
        ps[j] = a0;
        pd[j] = a1;
    }
    float h20 = 0.f, h21 = 0.f;
    #pragma unroll
    for (int i = 0; i < 16; i++) {
        h20 += h1[i] * sW2[i * 2];
        h21 += h1[i] * sW2[i * 2 + 1];
    }
    float al2s = h20 * sas2[0] + h21 * sas2[1];
    float al2d = h20 * sad2[0] + h21 * sad2[1];

    float4* pp = reinterpret_cast<float4*>(g_psrc + (size_t)n * 16);
    #pragma unroll
    for (int q = 0; q < 4; q++)
        pp[q] = make_float4(ps[4 * q], ps[4 * q + 1], ps[4 * q + 2], ps[4 * q + 3]);
    float4* pq = reinterpret_cast<float4*>(g_pdst + (size_t)n * 16);
    #pragma unroll
    for (int q = 0; q < 4; q++)
        pq[q] = make_float4(pd[4 * q], pd[4 * q + 1], pd[4 * q + 2], pd[4 * q + 3]);
    reinterpret_cast<float4*>(g_sd2)[n] = make_float4(h20, h21, al2s, al2d);
}

// ---------------- K4: edge MLP, two-phase cooperative gather (no swizzle) ----------------
#define EPB 512
__global__ void __launch_bounds__(256) k_edge2(const int* __restrict__ src,
                                               const int* __restrict__ dst,
                                               const float* __restrict__ ea,
                                               const float* __restrict__ mw0,
                                               const float* __restrict__ mb0,
                                               const float* __restrict__ mw1,
                                               const float* __restrict__ mb1,
                                               const float* __restrict__ mw2,
                                               const float* __restrict__ mb2,
                                               const float* __restrict__ mw3,
                                               const float* __restrict__ mb3,
                                               float* __restrict__ out_e) {
    __shared__ __align__(16) float4 s_w0q[12];      // mw0 rows 16..18, by quarter
    __shared__ __align__(16) float4 s_b0q[4];
    __shared__ __align__(16) ulonglong2 s_w1v[64];
    __shared__ __align__(16) ulonglong2 s_b1v[4];
    __shared__ __align__(16) ulonglong2 s_w2v[32];
    __shared__ __align__(16) ulonglong2 s_b2v[2];
    __shared__ __align__(16) ulonglong2 s_w3v[8];
    __shared__ __align__(16) ulonglong2 s_b3v[1];
    __shared__ float s_c2[4];
    __shared__ __align__(16) float s_t0[EPB * 20];  // staged t0, 80B stride (16B aligned)
    __shared__ int s_sidx[EPB];
    __shared__ int s_didx[EPB];

    int t = threadIdx.x;
    if (t < 12) s_w0q[t] = reinterpret_cast<const float4*>(mw0)[64 + t];
    else if (t < 16) s_b0q[t - 12] = reinterpret_cast<const float4*>(mb0)[t - 12];
    else if (t < 80) s_w1v[t - 16] = reinterpret_cast<const ulonglong2*>(mw1)[t - 16];
    else if (t < 84) s_b1v[t - 80] = reinterpret_cast<const ulonglong2*>(mb1)[t - 80];
    else if (t < 116) s_w2v[t - 84] = reinterpret_cast<const ulonglong2*>(mw2)[t - 84];
    else if (t < 118) s_b2v[t - 116] = reinterpret_cast<const ulonglong2*>(mb2)[t - 116];
    else if (t < 126) s_w3v[t - 118] = reinterpret_cast<const ulonglong2*>(mw3)[t - 118];
    else if (t < 127) s_b3v[0] = reinterpret_cast<const ulonglong2*>(mb3)[0];
    if (t >= 128 && t < 132) s_c2[t - 128] = g_c2[t - 128];
    __syncthreads();

    int ebase = blockIdx.x * EPB;

    // ---- phase 1: cooperative gather (4 lanes per edge, 64 edges/pass) + layer 0 ----
    {
        int q = t & 3;
        int er = t >> 2;  // 0..63
        float4 w0a = s_w0q[q], w0b = s_w0q[4 + q], w0c = s_w0q[8 + q], b0 = s_b0q[q];
        #pragma unroll
        for (int k = 0; k < 8; k++) {
            int el = k * 64 + er;
            int e = ebase + el;
            int s = src[e], d = dst[e];
            float ea0 = ea[e * 3], ea1 = ea[e * 3 + 1], ea2 = ea[e * 3 + 2];
            float4 ps = *reinterpret_cast<const float4*>(g_psrc + (size_t)s * 16 + q * 4);
            float4 pd = *reinterpret_cast<const float4*>(g_pdst + (size_t)d * 16 + q * 4);
            float4 v;
            v.x = fmaxf(ps.x + pd.x + b0.x + ea0 * w0a.x + ea1 * w0b.x + ea2 * w0c.x, 0.f);
            v.y = fmaxf(ps.y + pd.y + b0.y + ea0 * w0a.y + ea1 * w0b.y + ea2 * w0c.y, 0.f);
            v.z = fmaxf(ps.z + pd.z + b0.z + ea0 * w0a.z + ea1 * w0b.z + ea2 * w0c.z, 0.f);
            v.w = fmaxf(ps.w + pd.w + b0.w + ea0 * w0a.w + ea1 * w0b.w + ea2 * w0c.w, 0.f);
            *reinterpret_cast<float4*>(s_t0 + el * 20 + q * 4) = v;
            if (q == 0) {
                // register-sourced index staging (no extra loads)
                s_sidx[el] = s;
                s_didx[el] = d;
            }
        }
    }
    __syncthreads();

    // ---- phase 2: layers 1-3 for 2 edges/thread ----
    int eA = ebase + t;
    int eB = eA + 256;
    float t0A[16], t0B[16];
    {
        const float4* pA = reinterpret_cast<const float4*>(s_t0 + t * 20);
        const float4* pB = reinterpret_cast<const float4*>(s_t0 + (t + 256) * 20);
        #pragma unroll
        for (int qq = 0; qq < 4; qq++) {
            float4 a = pA[qq], b = pB[qq];
            t0A[4 * qq] = a.x; t0A[4 * qq + 1] = a.y; t0A[4 * qq + 2] = a.z; t0A[4 * qq + 3] = a.w;
            t0B[4 * qq] = b.x; t0B[4 * qq + 1] = b.y; t0B[4 * qq + 2] = b.z; t0B[4 * qq + 3] = b.w;
        }
    }
    int sA = s_sidx[t], dA = s_didx[t];
    int sB = s_sidx[t + 256], dB = s_didx[t + 256];
    float4 sdA = reinterpret_cast<const float4*>(g_sd2)[sA];  // {h20,h21,al2s,al2d}
    float4 sdB = reinterpret_cast<const float4*>(g_sd2)[sB];
    float ald2A = g_sd2[(size_t)dA * 4 + 3];
    float ald2B = g_sd2[(size_t)dB * 4 + 3];

    // layer 1: 16 -> 16
    u64 accA[8], accB[8];
    #pragma unroll
    for (int qq = 0; qq < 4; qq++) {
        ulonglong2 b = s_b1v[qq];
        accA[2 * qq] = b.x; accA[2 * qq + 1] = b.y;
        accB[2 * qq] = b.x; accB[2 * qq + 1] = b.y;
    }
    #pragma unroll
    for (int i = 0; i < 16; i++) {
        u64 biA = pack2(t0A[i]), biB = pack2(t0B[i]);
        #pragma unroll
        for (int qq = 0; qq < 4; qq++) {
            ulonglong2 w = s_w1v[i * 4 + qq];
            accA[2 * qq] = fma2(biA, w.x, accA[2 * qq]);
            accA[2 * qq + 1] = fma2(biA, w.y, accA[2 * qq + 1]);
            accB[2 * qq] = fma2(biB, w.x, accB[2 * qq]);
            accB[2 * qq + 1] = fma2(biB, w.y, accB[2 * qq + 1]);
        }
    }
    float t1A[16], t1B[16];
    #pragma unroll
    for (int p = 0; p < 8; p++) {
        float lo, hi;
        unpack2(accA[p], lo, hi); t1A[2 * p] = fmaxf(lo, 0.f); t1A[2 * p + 1] = fmaxf(hi, 0.f);
        unpack2(accB[p], lo, hi); t1B[2 * p] = fmaxf(lo, 0.f); t1B[2 * p + 1] = fmaxf(hi, 0.f);
    }

    // layer 2: 16 -> 8
    u64 c2A[4], c2B[4];
    {
        ulonglong2 b0 = s_b2v[0], b1 = s_b2v[1];
        c2A[0] = b0.x; c2A[1] = b0.y; c2A[2] = b1.x; c2A[3] = b1.y;
        c2B[0] = b0.x; c2B[1] = b0.y; c2B[2] = b1.x; c2B[3] = b1.y;
    }
    #pragma unroll
    for (int i = 0; i < 16; i++) {
        u64 biA = pack2(t1A[i]), biB = pack2(t1B[i]);
        ulonglong2 w0 = s_w2v[i * 2], w1r = s_w2v[i * 2 + 1];
        c2A[0] = fma2(biA, w0.x, c2A[0]); c2A[1] = fma2(biA, w0.y, c2A[1]);
        c2A[2] = fma2(biA, w1r.x, c2A[2]); c2A[3] = fma2(biA, w1r.y, c2A[3]);
        c2B[0] = fma2(biB, w0.x, c2B[0]); c2B[1] = fma2(biB, w0.y, c2B[1]);
        c2B[2] = fma2(biB, w1r.x, c2B[2]); c2B[3] = fma2(biB, w1r.y, c2B[3]);
    }
    float t2A[8], t2B[8];
    #pragma unroll
    for (int p = 0; p < 4; p++) {
        float lo, hi;
        unpack2(c2A[p], lo, hi); t2A[2 * p] = fmaxf(lo, 0.f); t2A[2 * p + 1] = fmaxf(hi, 0.f);
        unpack2(c2B[p], lo, hi); t2B[2 * p] = fmaxf(lo, 0.f); t2B[2 * p + 1] = fmaxf(hi, 0.f);
    }

    // layer 3: 8 -> 4
    u64 c3A0, c3A1, c3B0, c3B1;
    {
        ulonglong2 b = s_b3v[0];
        c3A0 = b.x; c3A1 = b.y; c3B0 = b.x; c3B1 = b.y;
    }
    #pragma unroll
    for (int i = 0; i < 8; i++) {
        u64 biA = pack2(t2A[i]), biB = pack2(t2B[i]);
        ulonglong2 w = s_w3v[i];
        c3A0 = fma2(biA, w.x, c3A0); c3A1 = fma2(biA, w.y, c3A1);
        c3B0 = fma2(biB, w.x, c3B0); c3B1 = fma2(biB, w.y, c3B1);
    }
    float e0A, e1A, e2A, e3A, e0B, e1B, e2B, e3B;
    unpack2(c3A0, e0A, e1A); unpack2(c3A1, e2A, e3A);
    unpack2(c3B0, e0B, e1B); unpack2(c3B1, e2B, e3B);

    // log_softmax per edge
    {
        float mx = fmaxf(fmaxf(e0A, e1A), fmaxf(e2A, e3A));
        float x0 = __expf(e0A - mx), x1 = __expf(e1A - mx), x2 = __expf(e2A - mx), x3 = __expf(e3A - mx);
        float lse = mx + __logf(x0 + x1 + x2 + x3);
        reinterpret_cast<float4*>(out_e)[eA] = make_float4(e0A - lse, e1A - lse, e2A - lse, e3A - lse);
    }
    {
        float mx = fmaxf(fmaxf(e0B, e1B), fmaxf(e2B, e3B));
        float x0 = __expf(e0B - mx), x1 = __expf(e1B - mx), x2 = __expf(e2B - mx), x3 = __expf(e3B - mx);
        float lse = mx + __logf(x0 + x1 + x2 + x3);
        reinterpret_cast<float4*>(out_e)[eB] = make_float4(e0B - lse, e1B - lse, e2B - lse, e3B - lse);
    }

    // layer-2 attention scatter
    {
        float alpha = sdA.z + ald2A + e0A * s_c2[0] + e1A * s_c2[1] + e2A * s_c2[2] + e3A * s_c2[3];
        float ex2 = __expf(leaky(alpha));
        red_v4(g_acc2 + (size_t)dA * 4, ex2 * sdA.x, ex2 * sdA.y, ex2, 0.f);
    }
    {
        float alpha = sdB.z + ald2B + e0B * s_c2[0] + e1B * s_c2[1] + e2B * s_c2[2] + e3B * s_c2[3];
        float ex2 = __expf(leaky(alpha));
        red_v4(g_acc2 + (size_t)dB * 4, ex2 * sdB.x, ex2 * sdB.y, ex2, 0.f);
    }

    // per-warp e-sum -> distributed partials (no barrier)
    float r0 = e0A + e0B, r1 = e1A + e1B, r2 = e2A + e2B, r3 = e3A + e3B;
    #pragma unroll
    for (int o = 16; o > 0; o >>= 1) {
        r0 += __shfl_down_sync(0xffffffffu, r0, o);
        r1 += __shfl_down_sync(0xffffffffu, r1, o);
        r2 += __shfl_down_sync(0xffffffffu, r2, o);
        r3 += __shfl_down_sync(0xffffffffu, r3, o);
    }
    if ((t & 31) == 0) {
        int slot = (blockIdx.x * 8 + (t >> 5)) & 255;
        red_v4(g_esum_part + slot * 4, r0, r1, r2, r3);
    }
}

// ---------------- K5: finalize layer 2 + node log_softmax (inline esum reduce) ----------------
__global__ void __launch_bounds__(256) k_node3(const float* __restrict__ b2,
                                               float* __restrict__ out_n) {
    __shared__ float4 redsh[8];
    int t = threadIdx.x;
    {
        float4 v = reinterpret_cast<const float4*>(g_esum_part)[t];
        #pragma unroll
        for (int o = 16; o > 0; o >>= 1) {
            v.x += __shfl_down_sync(0xffffffffu, v.x, o);
            v.y += __shfl_down_sync(0xffffffffu, v.y, o);
            v.z += __shfl_down_sync(0xffffffffu, v.z, o);
            v.w += __shfl_down_sync(0xffffffffu, v.w, o);
        }
        if ((t & 31) == 0) redsh[t >> 5] = v;
    }
    __syncthreads();
    float es0, es1, es2, es3;
    {
        float4 r = redsh[0];
        #pragma unroll
        for (int i = 1; i < 8; i++) { r.x += redsh[i].x; r.y += redsh[i].y; r.z += redsh[i].z; r.w += redsh[i].w; }
        es0 = r.x; es1 = r.y; es2 = r.z; es3 = r.w;
    }
    int n = blockIdx.x * 256 + t;
    if (n >= NN) return;
    const float invE = 1.f / (float)EE;
    float4 sd = reinterpret_cast<const float4*>(g_sd2)[n];  // {h20,h21,al2s,al2d}
    float a = sd.z + sd.w + invE * (es0 * g_c2[0] + es1 * g_c2[1] + es2 * g_c2[2] + es3 * g_c2[3]);
    float ex = __expf(leaky(a));
    float4 acc = reinterpret_cast<const float4*>(g_acc2)[n];
    float den = 1.f / (acc.z + ex + 1e-16f);
    float o0 = (acc.x + ex * sd.x) * den + b2[0];
    float o1 = (acc.y + ex * sd.y) * den + b2[1];
    float m = fmaxf(o0, o1);
    float l = m + __logf(__expf(o0 - m) + __expf(o1 - m));
    reinterpret_cast<float2*>(out_n)[n] = make_float2(o0 - l, o1 - l);
}

// ---------------- launch ----------------
extern "C" void kernel_launch(void* const* d_in, const int* in_sizes, int n_in,
                              void* d_out, int out_size) {
    const float* x   = (const float*)d_in[0];
    const float* ea  = (const float*)d_in[1];
    const float* W1  = (const float*)d_in[2];
    const float* as1 = (const float*)d_in[3];
    const float* ad1 = (const float*)d_in[4];
    const float* We1 = (const float*)d_in[5];
    const float* ae1 = (const float*)d_in[6];
    const float* b1  = (const float*)d_in[7];
    const float* mw0 = (const float*)d_in[8];
    const float* mb0 = (const float*)d_in[9];
    const float* mw1 = (const float*)d_in[10];
    const float* mb1 = (const float*)d_in[11];
    const float* mw2 = (const float*)d_in[12];
    const float* mb2 = (const float*)d_in[13];
    const float* mw3 = (const float*)d_in[14];
    const float* mb3 = (const float*)d_in[15];
    const float* W2  = (const float*)d_in[16];
    const float* as2 = (const float*)d_in[17];
    const float* ad2 = (const float*)d_in[18];
    const float* We2 = (const float*)d_in[19];
    const float* ae2 = (const float*)d_in[20];
    const float* b2  = (const float*)d_in[21];
    const int* ei    = (const int*)d_in[22];
    const int* srcp = ei;
    const int* dstp = ei + EE;
    float* out = (float*)d_out;

    k_node1<<<(NN + 255) / 256, 256>>>(W1, as1, ad1, We1, ae1, We2, ae2);
    k_edge1<<<EE / 512, 256>>>(srcp, dstp, ea, x);
    k_node2<<<(NN + 255) / 256, 256>>>(x, W1, b1, mw0, W2, as2, ad2);
    k_edge2<<<EE / EPB, 256>>>(srcp, dstp, ea, mw0, mb0, mw1, mb1, mw2, mb2, mw3, mb3,
                               out + 2 * NN);
    k_node3<<<(NN + 255) / 256, 256>>>(b2, out);
}